// round 15
// baseline (speedup 1.0000x reference)
#include <cuda_runtime.h>
#include <cuda_fp16.h>
#include <cstdint>

#define NN 50000
#define EE 800000
#define GG 64
#define HH 64
#define NB ((NN + 255) / 256)   // 196 scan blocks

// ---------------- scratch (device globals; no allocation allowed) ----------
__device__ __align__(16) int    g_degin_i[NN];
__device__ __align__(16) int    g_degout_i[NN];
__device__ __align__(16) int    g_rowptr[NN + 1];
__device__ __align__(16) int    g_cursor[NN];
__device__ __align__(16) int    g_blocksum[NB];
__device__ __align__(16) int    g_csr_src[EE];
__device__ __align__(16) float  g_norm_src[NN];
__device__ __align__(16) float  g_norm_dst[NN];
__device__ __align__(16) float  g_h0[NN * 4];      // layer-1 input features (fp32, 4-wide)
__device__ __align__(16) __half g_hA[NN * HH];     // hidden ping buffer (fp16)
__device__ __align__(16) __half g_hB[NN * HH];     // hidden pong buffer (fp16)
__device__ __align__(16) float  g_agg1[NN * 4];    // layer-1 aggregation (fp32)
__device__ __align__(16) float  g_gsum[GG * HH];   // graph pooling sums (fp32)
__device__ __align__(16) float  g_gcnt[GG];

// ---------------- helpers ---------------------------------------------------
__device__ __forceinline__ void red4(float* p, float4 v) {
    asm volatile("red.global.add.v4.f32 [%0], {%1, %2, %3, %4};"
                 :: "l"(p), "f"(v.x), "f"(v.y), "f"(v.z), "f"(v.w) : "memory");
}
__device__ __forceinline__ void acc8(float* a, uint4 u) {
    float2 f0 = __half22float2(*reinterpret_cast<__half2*>(&u.x));
    float2 f1 = __half22float2(*reinterpret_cast<__half2*>(&u.y));
    float2 f2 = __half22float2(*reinterpret_cast<__half2*>(&u.z));
    float2 f3 = __half22float2(*reinterpret_cast<__half2*>(&u.w));
    a[0] += f0.x; a[1] += f0.y; a[2] += f1.x; a[3] += f1.y;
    a[4] += f2.x; a[5] += f2.y; a[6] += f3.x; a[7] += f3.y;
}

// ---------------- CSR build --------------------------------------------------
__global__ void init_kernel() {
    int i = blockIdx.x * blockDim.x + threadIdx.x;
    if (i < NN) { g_degin_i[i] = 0; g_degout_i[i] = 0; }
    if (i < GG * HH) g_gsum[i] = 0.f;
    if (i < GG) g_gcnt[i] = 0.f;
}

__global__ void deg_kernel(const int* __restrict__ src, const int* __restrict__ dst) {
    int e = blockIdx.x * blockDim.x + threadIdx.x;
    if (e >= EE) return;
    atomicAdd(&g_degin_i[dst[e]], 1);
    atomicAdd(&g_degout_i[src[e]], 1);
}

__global__ void scanA_kernel() {
    __shared__ int s[256];
    int t = threadIdx.x;
    int n = blockIdx.x * 256 + t;
    int v = (n < NN) ? g_degin_i[n] : 0;
    s[t] = v;
    __syncthreads();
#pragma unroll
    for (int off = 1; off < 256; off <<= 1) {
        int add = (t >= off) ? s[t - off] : 0;
        __syncthreads();
        s[t] += add;
        __syncthreads();
    }
    if (n < NN) g_rowptr[n] = s[t] - v;
    if (t == 255) g_blocksum[blockIdx.x] = s[255];
}

__global__ void scanB_kernel() {
    __shared__ int s[256];
    int t = threadIdx.x;
    int v = (t < NB) ? g_blocksum[t] : 0;
    s[t] = v;
    __syncthreads();
#pragma unroll
    for (int off = 1; off < 256; off <<= 1) {
        int add = (t >= off) ? s[t - off] : 0;
        __syncthreads();
        s[t] += add;
        __syncthreads();
    }
    if (t < NB) g_blocksum[t] = s[t] - v;
    if (t == 0) g_rowptr[NN] = EE;
}

__global__ void scanC_feats_kernel(const int* __restrict__ graph_ids) {
    int n = blockIdx.x * blockDim.x + threadIdx.x;
    if (n >= NN) return;
    int r = g_rowptr[n] + g_blocksum[n >> 8];
    g_rowptr[n] = r;
    g_cursor[n] = r;

    float di = (float)g_degin_i[n];
    float dout = (float)g_degout_i[n];
    float h1 = di;
    float h2 = (di - 3.f > 0.f) ? 1.f : 0.f;
    float h3 = 3.f / di;
    float h4 = (di - 4.f > 0.f) ? 1.f : 0.f;
    float ns = rsqrtf(fmaxf(dout, 1.f));
    float nd = rsqrtf(fmaxf(di, 1.f));
    g_norm_src[n] = ns;
    g_norm_dst[n] = nd;
    reinterpret_cast<float4*>(g_h0)[n] =
        make_float4(h1 * ns, h2 * ns, h3 * ns, h4 * ns);
    atomicAdd(&g_gcnt[graph_ids[n]], 1.f);
}

__global__ void scatter_kernel(const int* __restrict__ src, const int* __restrict__ dst) {
    int e = blockIdx.x * blockDim.x + threadIdx.x;
    if (e >= EE) return;
    int d = dst[e];
    int pos = atomicAdd(&g_cursor[d], 1);
    g_csr_src[pos] = src[e];
}

// ---------------- layer 1 (4-wide, fp32) --------------------------------------
__global__ void agg1_kernel() {
    int n = blockIdx.x * blockDim.x + threadIdx.x;
    if (n >= NN) return;
    int e0 = g_rowptr[n], e1 = g_rowptr[n + 1];
    const float4* h4 = reinterpret_cast<const float4*>(g_h0);
    float4 acc = make_float4(0.f, 0.f, 0.f, 0.f);
    int e = e0;
    for (; e + 1 < e1; e += 2) {
        float4 v0 = h4[g_csr_src[e]];
        float4 v1 = h4[g_csr_src[e + 1]];
        acc.x += v0.x + v1.x; acc.y += v0.y + v1.y;
        acc.z += v0.z + v1.z; acc.w += v0.w + v1.w;
    }
    if (e < e1) {
        float4 v = h4[g_csr_src[e]];
        acc.x += v.x; acc.y += v.y; acc.z += v.z; acc.w += v.w;
    }
    reinterpret_cast<float4*>(g_agg1)[n] = acc;
}

// writes layer-1 output (pre-scaled by norm_src) into g_hA as fp16
__global__ void node_first_kernel(const float* __restrict__ W1, const float* __restrict__ b1) {
    int t = blockIdx.x * blockDim.x + threadIdx.x;
    if (t >= NN * HH) return;
    int n = t >> 6;
    int o = t & 63;
    float nd = g_norm_dst[n];
    float ns = g_norm_src[n];
    float4 x = reinterpret_cast<const float4*>(g_agg1)[n];
    float acc = b1[o];
    acc = fmaf(x.x * nd, W1[0 * HH + o], acc);
    acc = fmaf(x.y * nd, W1[1 * HH + o], acc);
    acc = fmaf(x.z * nd, W1[2 * HH + o], acc);
    acc = fmaf(x.w * nd, W1[3 * HH + o], acc);
    acc = fmaxf(acc, 0.f) * ns;
    g_hA[t] = __float2half_rn(acc);
}

// ---------------- fused layers 2..4 -------------------------------------------
// One warp = 4 nodes. Gather: per node, 16 lanes split into 2 groups of 8;
// group `pair` loads edge e+2it+pair as uint4 (8 fp16 feats, 16B). One unrolled
// step covers 8 edges -> serial depth deg/8. shfl_xor(8) combines the pair
// partials. GEMM in fp32 from smem (unchanged champion).
template <bool LAST>
__global__ void __launch_bounds__(256) layer_kernel(
        const __half* __restrict__ hin, __half* __restrict__ hout,
        const float* __restrict__ W, const float* __restrict__ b,
        const int* __restrict__ graph_ids) {
    __shared__ float Ws[HH * HH];
    __shared__ float bs[HH];
    __shared__ float xs[8][4][68];   // [warp][node-in-quad][64+pad]

    int tid = threadIdx.x;
    float4* Ws4 = reinterpret_cast<float4*>(Ws);
    const float4* Wg4 = reinterpret_cast<const float4*>(W);
    for (int i = tid; i < HH * HH / 4; i += 256) Ws4[i] = Wg4[i];
    if (tid < HH) bs[tid] = b[tid];
    __syncthreads();

    int warp = tid >> 5;
    int lane = tid & 31;
    int half_ = lane >> 4;     // 0 or 1
    int o4 = lane & 15;
    int pair = o4 >> 3;        // which edge of a pair this lane loads
    int slice8 = o4 & 7;       // which 16B slice of the 128B row

    const uint4* h4u = reinterpret_cast<const uint4*>(hin);  // row = 8 x 16B
    const int* __restrict__ csr = g_csr_src;

    const int NQ = NN / 4;     // 12500 quads

    for (int quad = blockIdx.x * 8 + warp; quad < NQ; quad += gridDim.x * 8) {
        // ---- gather: this lane helps nodes (half_) and (half_+2) of the quad
#pragma unroll
        for (int g = 0; g < 2; g++) {
            int q = half_ + 2 * g;
            int n = quad * 4 + q;
            int e0 = g_rowptr[n], e1 = g_rowptr[n + 1];
            float a[8] = {0.f, 0.f, 0.f, 0.f, 0.f, 0.f, 0.f, 0.f};
            int e = e0;
            for (; e + 7 < e1; e += 8) {
                int s0 = csr[e + 0 + pair];
                int s1 = csr[e + 2 + pair];
                int s2 = csr[e + 4 + pair];
                int s3 = csr[e + 6 + pair];
                uint4 u0 = h4u[s0 * 8 + slice8];
                uint4 u1 = h4u[s1 * 8 + slice8];
                uint4 u2 = h4u[s2 * 8 + slice8];
                uint4 u3 = h4u[s3 * 8 + slice8];
                acc8(a, u0); acc8(a, u1); acc8(a, u2); acc8(a, u3);
            }
            for (; e < e1; e += 2) {
                if (e + pair < e1) {
                    int s = csr[e + pair];
                    uint4 u = h4u[s * 8 + slice8];
                    acc8(a, u);
                }
            }
            // combine the two pair-groups' partials (same slice, different edges)
#pragma unroll
            for (int i = 0; i < 8; i++)
                a[i] += __shfl_xor_sync(0xFFFFFFFF, a[i], 8);
            float nd = g_norm_dst[n];
            // each lane stores the float4 half it owns: [slice8*8 + pair*4 ..]
            float4 st;
            st.x = a[pair * 4 + 0] * nd;
            st.y = a[pair * 4 + 1] * nd;
            st.z = a[pair * 4 + 2] * nd;
            st.w = a[pair * 4 + 3] * nd;
            reinterpret_cast<float4*>(&xs[warp][q][0])[slice8 * 2 + pair] = st;
        }
        __syncwarp();
        // ---- GEMM: slice o4 for nodes q0=2*half_, q1=2*half_+1 (shared W loads)
        {
            int q0 = 2 * half_;
            int n0 = quad * 4 + q0;
            int n1 = n0 + 1;
            float4 bb = reinterpret_cast<float4*>(bs)[o4];
            float4 r0 = bb, r1 = bb;
            const float4* x0row = reinterpret_cast<const float4*>(&xs[warp][q0][0]);
            const float4* x1row = reinterpret_cast<const float4*>(&xs[warp][q0 + 1][0]);
#pragma unroll
            for (int k4 = 0; k4 < 16; k4++) {
                float4 x0v = x0row[k4];
                float4 x1v = x1row[k4];
#pragma unroll
                for (int j = 0; j < 4; j++) {
                    float4 w = Ws4[(k4 * 4 + j) * 16 + o4];
                    float a = (j == 0) ? x0v.x : (j == 1) ? x0v.y : (j == 2) ? x0v.z : x0v.w;
                    float c = (j == 0) ? x1v.x : (j == 1) ? x1v.y : (j == 2) ? x1v.z : x1v.w;
                    r0.x = fmaf(a, w.x, r0.x);
                    r0.y = fmaf(a, w.y, r0.y);
                    r0.z = fmaf(a, w.z, r0.z);
                    r0.w = fmaf(a, w.w, r0.w);
                    r1.x = fmaf(c, w.x, r1.x);
                    r1.y = fmaf(c, w.y, r1.y);
                    r1.z = fmaf(c, w.z, r1.z);
                    r1.w = fmaf(c, w.w, r1.w);
                }
            }
            r0.x = fmaxf(r0.x, 0.f); r0.y = fmaxf(r0.y, 0.f);
            r0.z = fmaxf(r0.z, 0.f); r0.w = fmaxf(r0.w, 0.f);
            r1.x = fmaxf(r1.x, 0.f); r1.y = fmaxf(r1.y, 0.f);
            r1.z = fmaxf(r1.z, 0.f); r1.w = fmaxf(r1.w, 0.f);
            if (!LAST) {
                float ns0 = g_norm_src[n0];
                float ns1 = g_norm_src[n1];
                r0.x *= ns0; r0.y *= ns0; r0.z *= ns0; r0.w *= ns0;
                r1.x *= ns1; r1.y *= ns1; r1.z *= ns1; r1.w *= ns1;
                __half2 a0 = __floats2half2_rn(r0.x, r0.y);
                __half2 a1 = __floats2half2_rn(r0.z, r0.w);
                __half2 c0 = __floats2half2_rn(r1.x, r1.y);
                __half2 c1 = __floats2half2_rn(r1.z, r1.w);
                uint2 s0, s1;
                s0.x = *reinterpret_cast<unsigned*>(&a0);
                s0.y = *reinterpret_cast<unsigned*>(&a1);
                s1.x = *reinterpret_cast<unsigned*>(&c0);
                s1.y = *reinterpret_cast<unsigned*>(&c1);
                reinterpret_cast<uint2*>(hout)[n0 * 16 + o4] = s0;
                reinterpret_cast<uint2*>(hout)[n1 * 16 + o4] = s1;
            } else {
                int g0 = graph_ids[n0];
                int g1 = graph_ids[n1];
                red4(&g_gsum[g0 * HH + o4 * 4], r0);
                red4(&g_gsum[g1 * HH + o4 * 4], r1);
            }
        }
        __syncwarp();
    }
}

// final head: per-graph mean, dot with Wout, + bout, sigmoid
__global__ void out_kernel(const float* __restrict__ Wout, const float* __restrict__ bout,
                           float* __restrict__ out) {
    __shared__ float s[HH];
    int g = blockIdx.x;
    int t = threadIdx.x;
    float inv = 1.f / g_gcnt[g];
    float v = g_gsum[g * HH + t] * inv * Wout[t];
    s[t] = v;
    __syncthreads();
    if (t < 32) {
        float x = s[t] + s[t + 32];
#pragma unroll
        for (int off = 16; off > 0; off >>= 1)
            x += __shfl_xor_sync(0xFFFFFFFF, x, off);
        if (t == 0) out[g] = 1.f / (1.f + expf(-(x + bout[0])));
    }
}

// ---------------- launch -----------------------------------------------------
extern "C" void kernel_launch(void* const* d_in, const int* in_sizes, int n_in,
                              void* d_out, int out_size) {
    const int*   src  = (const int*)d_in[0];
    const int*   dst  = (const int*)d_in[1];
    const int*   gids = (const int*)d_in[2];
    const float* W1   = (const float*)d_in[3];
    const float* b1   = (const float*)d_in[4];
    const float* W2   = (const float*)d_in[5];
    const float* b2   = (const float*)d_in[6];
    const float* W3   = (const float*)d_in[7];
    const float* b3   = (const float*)d_in[8];
    const float* W4   = (const float*)d_in[9];
    const float* b4   = (const float*)d_in[10];
    const float* Wout = (const float*)d_in[11];
    const float* bout = (const float*)d_in[12];
    float* out = (float*)d_out;

    __half *hA, *hB;
    cudaGetSymbolAddress((void**)&hA, g_hA);
    cudaGetSymbolAddress((void**)&hB, g_hB);

    const int T = 256;
    const int gridN  = (NN + T - 1) / T;
    const int gridE  = (EE + T - 1) / T;
    const int gridNH = (NN * HH + T - 1) / T;
    const int gridLayer = 888;

    // CSR build (once; reused for all 4 layers)
    init_kernel<<<gridN, T>>>();
    deg_kernel<<<gridE, T>>>(src, dst);
    scanA_kernel<<<NB, 256>>>();
    scanB_kernel<<<1, 256>>>();
    scanC_feats_kernel<<<gridN, T>>>(gids);
    scatter_kernel<<<gridE, T>>>(src, dst);

    // layer 1 (4-wide fp32): agg from g_h0, output (H-wide fp16) into hA
    agg1_kernel<<<gridN, T>>>();
    node_first_kernel<<<gridNH, T>>>(W1, b1);

    // layers 2..4 fused, double-buffered fp16: A->B, B->A, A->pool
    layer_kernel<false><<<gridLayer, T>>>(hA, hB, W2, b2, gids);
    layer_kernel<false><<<gridLayer, T>>>(hB, hA, W3, b3, gids);
    layer_kernel<true ><<<gridLayer, T>>>(hA, hB, W4, b4, gids);

    out_kernel<<<GG, HH>>>(Wout, bout, out);
}

// round 16
// speedup vs baseline: 1.0135x; 1.0135x over previous
#include <cuda_runtime.h>
#include <cuda_fp16.h>
#include <cstdint>

#define NN 50000
#define EE 800000
#define GG 64
#define HH 64
#define NB ((NN + 255) / 256)   // 196 scan blocks

// ---------------- scratch (device globals; no allocation allowed) ----------
__device__ __align__(16) int    g_degin_i[NN];
__device__ __align__(16) int    g_degout_i[NN];
__device__ __align__(16) int    g_rowptr[NN + 1];
__device__ __align__(16) int    g_cursor[NN];
__device__ __align__(16) int    g_blocksum[NB];
__device__ __align__(16) int    g_csr_src[EE];
__device__ __align__(16) float  g_norm_src[NN];
__device__ __align__(16) float  g_norm_dst[NN];
__device__ __align__(16) float  g_h0[NN * 4];      // layer-1 input features (fp32, 4-wide)
__device__ __align__(16) __half g_hA[NN * HH];     // hidden ping buffer (fp16)
__device__ __align__(16) __half g_hB[NN * HH];     // hidden pong buffer (fp16)
__device__ __align__(16) float  g_agg1[NN * 4];    // layer-1 aggregation (fp32)
__device__ __align__(16) float  g_gsum[GG * HH];   // graph pooling sums (fp32)
__device__ __align__(16) float  g_gcnt[GG];

__device__ unsigned g_scan_count;                  // last-block tracker (self-resetting)
__device__ unsigned g_bar_count;                   // grid barrier (self-resetting)
__device__ volatile unsigned g_bar_phase;          // monotonic; waits are relative

// ---------------- helpers ---------------------------------------------------
__device__ __forceinline__ void red4(float* p, float4 v) {
    asm volatile("red.global.add.v4.f32 [%0], {%1, %2, %3, %4};"
                 :: "l"(p), "f"(v.x), "f"(v.y), "f"(v.z), "f"(v.w) : "memory");
}

__device__ __forceinline__ void grid_sync(unsigned target) {
    __syncthreads();
    if (threadIdx.x == 0) {
        __threadfence();
        unsigned old = atomicAdd(&g_bar_count, 1u);
        if (old == gridDim.x - 1u) {
            atomicExch(&g_bar_count, 0u);
            __threadfence();
            g_bar_phase = target;              // release
        } else {
            while (g_bar_phase < target) { }   // spin
        }
        __threadfence();                        // acquire
    }
    __syncthreads();
}

// ---------------- CSR build --------------------------------------------------
__global__ void init_kernel() {
    int i = blockIdx.x * blockDim.x + threadIdx.x;
    if (i < NN) { g_degin_i[i] = 0; g_degout_i[i] = 0; }
    if (i < GG * HH) g_gsum[i] = 0.f;
    if (i < GG) g_gcnt[i] = 0.f;
}

__global__ void deg_kernel(const int* __restrict__ src, const int* __restrict__ dst) {
    int e = blockIdx.x * blockDim.x + threadIdx.x;
    if (e >= EE) return;
    atomicAdd(&g_degin_i[dst[e]], 1);
    atomicAdd(&g_degout_i[src[e]], 1);
}

// scanA + (last block) scanB fused
__global__ void scanAB_kernel() {
    __shared__ int s[256];
    __shared__ bool isLast;
    int t = threadIdx.x;
    int n = blockIdx.x * 256 + t;
    int v = (n < NN) ? g_degin_i[n] : 0;
    s[t] = v;
    __syncthreads();
#pragma unroll
    for (int off = 1; off < 256; off <<= 1) {
        int add = (t >= off) ? s[t - off] : 0;
        __syncthreads();
        s[t] += add;
        __syncthreads();
    }
    if (n < NN) g_rowptr[n] = s[t] - v;           // exclusive within block
    if (t == 255) g_blocksum[blockIdx.x] = s[255];
    __threadfence();
    __syncthreads();
    if (t == 0) {
        unsigned c = atomicAdd(&g_scan_count, 1u);
        isLast = (c == gridDim.x - 1u);
    }
    __syncthreads();
    if (isLast) {
        int v2 = (t < NB) ? g_blocksum[t] : 0;
        s[t] = v2;
        __syncthreads();
#pragma unroll
        for (int off = 1; off < 256; off <<= 1) {
            int add = (t >= off) ? s[t - off] : 0;
            __syncthreads();
            s[t] += add;
            __syncthreads();
        }
        if (t < NB) g_blocksum[t] = s[t] - v2;    // exclusive
        if (t == 0) {
            g_rowptr[NN] = EE;
            g_scan_count = 0;                      // reset for graph replay
        }
    }
}

__global__ void scanC_feats_kernel(const int* __restrict__ graph_ids) {
    int n = blockIdx.x * blockDim.x + threadIdx.x;
    if (n >= NN) return;
    int r = g_rowptr[n] + g_blocksum[n >> 8];
    g_rowptr[n] = r;
    g_cursor[n] = r;

    float di = (float)g_degin_i[n];
    float dout = (float)g_degout_i[n];
    float h1 = di;
    float h2 = (di - 3.f > 0.f) ? 1.f : 0.f;
    float h3 = 3.f / di;
    float h4 = (di - 4.f > 0.f) ? 1.f : 0.f;
    float ns = rsqrtf(fmaxf(dout, 1.f));
    float nd = rsqrtf(fmaxf(di, 1.f));
    g_norm_src[n] = ns;
    g_norm_dst[n] = nd;
    reinterpret_cast<float4*>(g_h0)[n] =
        make_float4(h1 * ns, h2 * ns, h3 * ns, h4 * ns);
    atomicAdd(&g_gcnt[graph_ids[n]], 1.f);
}

__global__ void scatter_kernel(const int* __restrict__ src, const int* __restrict__ dst) {
    int e = blockIdx.x * blockDim.x + threadIdx.x;
    if (e >= EE) return;
    int d = dst[e];
    int pos = atomicAdd(&g_cursor[d], 1);
    g_csr_src[pos] = src[e];
}

// ---------------- layer 1 (4-wide, fp32) --------------------------------------
__global__ void agg1_kernel() {
    int n = blockIdx.x * blockDim.x + threadIdx.x;
    if (n >= NN) return;
    int e0 = g_rowptr[n], e1 = g_rowptr[n + 1];
    const float4* h4 = reinterpret_cast<const float4*>(g_h0);
    float4 acc = make_float4(0.f, 0.f, 0.f, 0.f);
    int e = e0;
    for (; e + 1 < e1; e += 2) {
        float4 v0 = h4[g_csr_src[e]];
        float4 v1 = h4[g_csr_src[e + 1]];
        acc.x += v0.x + v1.x; acc.y += v0.y + v1.y;
        acc.z += v0.z + v1.z; acc.w += v0.w + v1.w;
    }
    if (e < e1) {
        float4 v = h4[g_csr_src[e]];
        acc.x += v.x; acc.y += v.y; acc.z += v.z; acc.w += v.w;
    }
    reinterpret_cast<float4*>(g_agg1)[n] = acc;
}

__global__ void node_first_kernel(const float* __restrict__ W1, const float* __restrict__ b1) {
    int t = blockIdx.x * blockDim.x + threadIdx.x;
    if (t >= NN * HH) return;
    int n = t >> 6;
    int o = t & 63;
    float nd = g_norm_dst[n];
    float ns = g_norm_src[n];
    float4 x = reinterpret_cast<const float4*>(g_agg1)[n];
    float acc = b1[o];
    acc = fmaf(x.x * nd, W1[0 * HH + o], acc);
    acc = fmaf(x.y * nd, W1[1 * HH + o], acc);
    acc = fmaf(x.z * nd, W1[2 * HH + o], acc);
    acc = fmaf(x.w * nd, W1[3 * HH + o], acc);
    acc = fmaxf(acc, 0.f) * ns;
    g_hA[t] = __float2half_rn(acc);
}

// ---------------- fused layers 2..4 (R14 champion body) ------------------------
// One warp = 4 nodes; gather fp16 rows (8B/lane/edge), fp32 accumulate; GEMM
// fp32 from smem with W loads shared across 2 nodes. LAST: pool + fused head.
template <bool LAST>
__global__ void __launch_bounds__(256) layer_kernel(
        const __half* __restrict__ hin, __half* __restrict__ hout,
        const float* __restrict__ W, const float* __restrict__ b,
        const int* __restrict__ graph_ids,
        const float* __restrict__ Wout, const float* __restrict__ bout,
        float* __restrict__ out) {
    __shared__ float Ws[HH * HH];
    __shared__ float bs[HH];
    __shared__ float xs[8][4][68];   // [warp][node-in-quad][64+pad]

    int tid = threadIdx.x;
    float4* Ws4 = reinterpret_cast<float4*>(Ws);
    const float4* Wg4 = reinterpret_cast<const float4*>(W);
    for (int i = tid; i < HH * HH / 4; i += 256) Ws4[i] = Wg4[i];
    if (tid < HH) bs[tid] = b[tid];

    unsigned bar0 = 0;
    if (LAST && tid == 0) bar0 = g_bar_phase;
    __syncthreads();

    int warp = tid >> 5;
    int lane = tid & 31;
    int half_ = lane >> 4;     // 0 or 1
    int o4 = lane & 15;        // 8B slice index (4 features)

    const uint2* h2 = reinterpret_cast<const uint2*>(hin);  // row = 16 x 8B
    const int* __restrict__ csr = g_csr_src;

    const int NQ = NN / 4;     // 12500 quads

    for (int quad = blockIdx.x * 8 + warp; quad < NQ; quad += gridDim.x * 8) {
        // ---- gather: this lane handles nodes (half_) and (half_+2) of the quad
#pragma unroll
        for (int g = 0; g < 2; g++) {
            int q = half_ + 2 * g;
            int n = quad * 4 + q;
            int e0 = g_rowptr[n], e1 = g_rowptr[n + 1];
            float4 acc = make_float4(0.f, 0.f, 0.f, 0.f);
            int e = e0;
            for (; e + 3 < e1; e += 4) {
                int s0 = csr[e], s1 = csr[e + 1], s2 = csr[e + 2], s3 = csr[e + 3];
                uint2 u0 = h2[s0 * 16 + o4];
                uint2 u1 = h2[s1 * 16 + o4];
                uint2 u2 = h2[s2 * 16 + o4];
                uint2 u3 = h2[s3 * 16 + o4];
#pragma unroll
                for (int m = 0; m < 4; m++) {
                    uint2 u = (m == 0) ? u0 : (m == 1) ? u1 : (m == 2) ? u2 : u3;
                    float2 f0 = __half22float2(*reinterpret_cast<__half2*>(&u.x));
                    float2 f1 = __half22float2(*reinterpret_cast<__half2*>(&u.y));
                    acc.x += f0.x; acc.y += f0.y; acc.z += f1.x; acc.w += f1.y;
                }
            }
            for (; e < e1; e++) {
                uint2 u = h2[csr[e] * 16 + o4];
                float2 f0 = __half22float2(*reinterpret_cast<__half2*>(&u.x));
                float2 f1 = __half22float2(*reinterpret_cast<__half2*>(&u.y));
                acc.x += f0.x; acc.y += f0.y; acc.z += f1.x; acc.w += f1.y;
            }
            float nd = g_norm_dst[n];
            acc.x *= nd; acc.y *= nd; acc.z *= nd; acc.w *= nd;
            reinterpret_cast<float4*>(&xs[warp][q][0])[o4] = acc;
        }
        __syncwarp();
        // ---- GEMM: slice o4 for nodes q0=2*half_, q1=2*half_+1 (shared W loads)
        {
            int q0 = 2 * half_;
            int n0 = quad * 4 + q0;
            int n1 = n0 + 1;
            float4 bb = reinterpret_cast<float4*>(bs)[o4];
            float4 r0 = bb, r1 = bb;
            const float4* x0row = reinterpret_cast<const float4*>(&xs[warp][q0][0]);
            const float4* x1row = reinterpret_cast<const float4*>(&xs[warp][q0 + 1][0]);
#pragma unroll
            for (int k4 = 0; k4 < 16; k4++) {
                float4 x0v = x0row[k4];
                float4 x1v = x1row[k4];
#pragma unroll
                for (int j = 0; j < 4; j++) {
                    float4 w = Ws4[(k4 * 4 + j) * 16 + o4];
                    float a = (j == 0) ? x0v.x : (j == 1) ? x0v.y : (j == 2) ? x0v.z : x0v.w;
                    float c = (j == 0) ? x1v.x : (j == 1) ? x1v.y : (j == 2) ? x1v.z : x1v.w;
                    r0.x = fmaf(a, w.x, r0.x);
                    r0.y = fmaf(a, w.y, r0.y);
                    r0.z = fmaf(a, w.z, r0.z);
                    r0.w = fmaf(a, w.w, r0.w);
                    r1.x = fmaf(c, w.x, r1.x);
                    r1.y = fmaf(c, w.y, r1.y);
                    r1.z = fmaf(c, w.z, r1.z);
                    r1.w = fmaf(c, w.w, r1.w);
                }
            }
            r0.x = fmaxf(r0.x, 0.f); r0.y = fmaxf(r0.y, 0.f);
            r0.z = fmaxf(r0.z, 0.f); r0.w = fmaxf(r0.w, 0.f);
            r1.x = fmaxf(r1.x, 0.f); r1.y = fmaxf(r1.y, 0.f);
            r1.z = fmaxf(r1.z, 0.f); r1.w = fmaxf(r1.w, 0.f);
            if (!LAST) {
                float ns0 = g_norm_src[n0];
                float ns1 = g_norm_src[n1];
                r0.x *= ns0; r0.y *= ns0; r0.z *= ns0; r0.w *= ns0;
                r1.x *= ns1; r1.y *= ns1; r1.z *= ns1; r1.w *= ns1;
                __half2 a0 = __floats2half2_rn(r0.x, r0.y);
                __half2 a1 = __floats2half2_rn(r0.z, r0.w);
                __half2 c0 = __floats2half2_rn(r1.x, r1.y);
                __half2 c1 = __floats2half2_rn(r1.z, r1.w);
                uint2 s0, s1;
                s0.x = *reinterpret_cast<unsigned*>(&a0);
                s0.y = *reinterpret_cast<unsigned*>(&a1);
                s1.x = *reinterpret_cast<unsigned*>(&c0);
                s1.y = *reinterpret_cast<unsigned*>(&c1);
                reinterpret_cast<uint2*>(hout)[n0 * 16 + o4] = s0;
                reinterpret_cast<uint2*>(hout)[n1 * 16 + o4] = s1;
            } else {
                int g0 = graph_ids[n0];
                int g1 = graph_ids[n1];
                red4(&g_gsum[g0 * HH + o4 * 4], r0);
                red4(&g_gsum[g1 * HH + o4 * 4], r1);
            }
        }
        __syncwarp();
    }

    if (LAST) {
        grid_sync(bar0 + 1);   // pooling complete across the grid
        if (blockIdx.x < GG) {
            int g = blockIdx.x;
            if (tid < HH)
                bs[tid] = g_gsum[g * HH + tid] * (1.f / g_gcnt[g]) * Wout[tid];
            __syncthreads();
            if (tid < 32) {
                float x = bs[tid] + bs[tid + 32];
#pragma unroll
                for (int off = 16; off > 0; off >>= 1)
                    x += __shfl_xor_sync(0xFFFFFFFF, x, off);
                if (tid == 0) out[g] = 1.f / (1.f + expf(-(x + bout[0])));
            }
        }
    }
}

// ---------------- launch -----------------------------------------------------
extern "C" void kernel_launch(void* const* d_in, const int* in_sizes, int n_in,
                              void* d_out, int out_size) {
    const int*   src  = (const int*)d_in[0];
    const int*   dst  = (const int*)d_in[1];
    const int*   gids = (const int*)d_in[2];
    const float* W1   = (const float*)d_in[3];
    const float* b1   = (const float*)d_in[4];
    const float* W2   = (const float*)d_in[5];
    const float* b2   = (const float*)d_in[6];
    const float* W3   = (const float*)d_in[7];
    const float* b3   = (const float*)d_in[8];
    const float* W4   = (const float*)d_in[9];
    const float* b4   = (const float*)d_in[10];
    const float* Wout = (const float*)d_in[11];
    const float* bout = (const float*)d_in[12];
    float* out = (float*)d_out;

    __half *hA, *hB;
    cudaGetSymbolAddress((void**)&hA, g_hA);
    cudaGetSymbolAddress((void**)&hB, g_hB);

    const int T = 256;
    const int gridN  = (NN + T - 1) / T;
    const int gridE  = (EE + T - 1) / T;
    const int gridNH = (NN * HH + T - 1) / T;

    // one co-resident wave for the layer kernels (needed for the LAST barrier)
    int smCount = 148, occL = 6;
    cudaDeviceGetAttribute(&smCount, cudaDevAttrMultiProcessorCount, 0);
    cudaOccupancyMaxActiveBlocksPerMultiprocessor(&occL, layer_kernel<true>, T, 0);
    if (occL < 1) occL = 1;
    int gridLayer = smCount * occL;

    // CSR build (once; reused for all 4 layers)
    init_kernel<<<gridN, T>>>();
    deg_kernel<<<gridE, T>>>(src, dst);
    scanAB_kernel<<<NB, 256>>>();
    scanC_feats_kernel<<<gridN, T>>>(gids);
    scatter_kernel<<<gridE, T>>>(src, dst);

    // layer 1 (4-wide fp32): agg from g_h0, output (H-wide fp16) into hA
    agg1_kernel<<<gridN, T>>>();
    node_first_kernel<<<gridNH, T>>>(W1, b1);

    // layers 2..4 fused, double-buffered fp16: A->B, B->A, A->pool(+head)
    layer_kernel<false><<<gridLayer, T>>>(hA, hB, W2, b2, gids, Wout, bout, out);
    layer_kernel<false><<<gridLayer, T>>>(hB, hA, W3, b3, gids, Wout, bout, out);
    layer_kernel<true ><<<gridLayer, T>>>(hA, hB, W4, b4, gids, Wout, bout, out);
}